// round 4
// baseline (speedup 1.0000x reference)
#include <cuda_runtime.h>
#include <cuda_bf16.h>
#include <math.h>

#define Bc 128
#define Tc 1024
#define Ic 128
#define Hc 1024
#define Oc 128
#define Gc 4096
#define KW 1280   // packed K: 1024 (W_eff) + 128 (W_x) + 128 (W_o/delta)
#define NBLK 132  // 128 gate CTAs + 4 y CTAs, all co-resident (148 SMs)

typedef unsigned long long ull;

// ---------- device scratch (static; no runtime allocation) ----------
__device__ float g_W[(size_t)Gc * KW];   // packed weights, grouped by gate-block
__device__ float g_bp[Gc];               // packed effective bias
__device__ float g_h[2 * Bc * Hc];       // double-buffered hidden state
__device__ float g_c[Bc * Hc];           // cell state
__device__ float g_delta[Bc * Oc];       // t=0 carry correction

// ---------- grid barrier state ----------
__device__ unsigned g_cnt = 0;
__device__ volatile unsigned g_gen = 0;

__device__ __forceinline__ void grid_sync() {
    __syncthreads();
    if (threadIdx.x == 0) {
        __threadfence();                      // release (drains writes, CCTL.IVALL)
        unsigned my = g_gen;
        if (atomicAdd(&g_cnt, 1) == NBLK - 1) {
            g_cnt = 0;
            __threadfence();                  // order cnt reset before gen bump
            g_gen = my + 1;
        } else {
            while (g_gen == my) { }
        }
        __threadfence();                      // acquire: invalidate L1D before reads
    }
    __syncthreads();
}

__device__ __forceinline__ void ffma2(ull& d, ull a, ull b) {
    asm("fma.rn.f32x2 %0, %1, %2, %0;" : "+l"(d) : "l"(a), "l"(b));
}
__device__ __forceinline__ float2 asf2(ull v) {
    float2 r; asm("mov.b64 {%0,%1}, %2;" : "=f"(r.x), "=f"(r.y) : "l"(v)); return r;
}
__device__ __forceinline__ float sigm(float x) { return 1.0f / (1.0f + expf(-x)); }

// swizzled pair store: row stride 32 floats (128B), pair p at slot p ^ ((row>>1)&15)
__device__ __forceinline__ void sts_swz(float* buf, int row, int c4, float4 v) {
    int z = (row >> 1) & 15;
    int p0 = c4 << 1;
    float2* s0 = (float2*)(buf + row * 32 + (((p0    ) ^ z) << 1));
    float2* s1 = (float2*)(buf + row * 32 + (((p0 + 1) ^ z) << 1));
    *s0 = make_float2(v.x, v.y);
    *s1 = make_float2(v.z, v.w);
}

// ---------------- precompute: pack effective weights ----------------
// Block cb owns local rows r=0..31 <-> global gate row gr=(r>>3)*1024 + cb*8 + (r&7).
// g_W[cb*32+r][0:1024]    = W_hh[gr] + sum_o W_ih[gr][128+o] * W_out[o]
// g_W[cb*32+r][1024:1280] = W_ih[gr][0:256]
// g_bp[cb*32+r]           = b_ih+b_hh + sum_o W_ih[gr][128+o]*b_out[o]
__global__ void __launch_bounds__(256, 1) pack_weights(
    const float* __restrict__ Wih, const float* __restrict__ Whh,
    const float* __restrict__ bih, const float* __restrict__ bhh,
    const float* __restrict__ Wout, const float* __restrict__ bout)
{
    __shared__ float ao[32][129];
    __shared__ float wos[128][33];
    int cb = blockIdx.x, tid = threadIdx.x;

    for (int i = 0; i < 4; i++) {                       // 32 rows x 32 float4
        int idx = i * 256 + tid;
        int r = idx >> 5, c4 = idx & 31;
        int gr = ((r >> 3) << 10) + (cb << 3) + (r & 7);
        float4 v = *(const float4*)(Wih + (size_t)gr * 256 + 128 + (c4 << 2));
        ao[r][(c4 << 2) + 0] = v.x; ao[r][(c4 << 2) + 1] = v.y;
        ao[r][(c4 << 2) + 2] = v.z; ao[r][(c4 << 2) + 3] = v.w;
    }
    __syncthreads();

    int r = tid >> 3;
    int gr = ((r >> 3) << 10) + (cb << 3) + (r & 7);
    int kk0 = (tid & 7) << 2;
    for (int kc = 0; kc < 32; kc++) {
        for (int i = 0; i < 4; i++) {                   // stage W_out[:,kc*32..+32]
            int idx = i * 256 + tid;
            int o = idx >> 3, c4 = idx & 7;
            float4 v = *(const float4*)(Wout + (size_t)o * Hc + (kc << 5) + (c4 << 2));
            wos[o][(c4 << 2) + 0] = v.x; wos[o][(c4 << 2) + 1] = v.y;
            wos[o][(c4 << 2) + 2] = v.z; wos[o][(c4 << 2) + 3] = v.w;
        }
        __syncthreads();
        float a0 = 0.f, a1 = 0.f, a2 = 0.f, a3 = 0.f;
#pragma unroll 4
        for (int o = 0; o < 128; o++) {
            float a = ao[r][o];
            a0 += a * wos[o][kk0 + 0]; a1 += a * wos[o][kk0 + 1];
            a2 += a * wos[o][kk0 + 2]; a3 += a * wos[o][kk0 + 3];
        }
        int k = (kc << 5) + kk0;
        const float* hh = Whh + (size_t)gr * Hc + k;
        float* dst = g_W + (size_t)(cb * 32 + r) * KW + k;
        dst[0] = hh[0] + a0; dst[1] = hh[1] + a1;
        dst[2] = hh[2] + a2; dst[3] = hh[3] + a3;
        __syncthreads();
    }
    for (int i = 0; i < 8; i++) {                       // copy W_ih rows verbatim
        int idx = i * 256 + tid;
        int rr = idx >> 6, c4 = idx & 63;
        int grr = ((rr >> 3) << 10) + (cb << 3) + (rr & 7);
        float4 v = *(const float4*)(Wih + (size_t)grr * 256 + (c4 << 2));
        *(float4*)(g_W + (size_t)(cb * 32 + rr) * KW + 1024 + (c4 << 2)) = v;
    }
    if (tid < 32) {
        int grr = ((tid >> 3) << 10) + (cb << 3) + (tid & 7);
        float s = bih[grr] + bhh[grr];
        for (int o = 0; o < 128; o++) s += ao[tid][o] * bout[o];
        g_bp[cb * 32 + tid] = s;
    }
}

// ---------------- init state + t=0 correction ----------------
__global__ void __launch_bounds__(256, 1) delta_init(
    const float* __restrict__ hn, const float* __restrict__ cn,
    const float* __restrict__ outt,
    const float* __restrict__ Wout, const float* __restrict__ bout)
{
    __shared__ __align__(16) float hs[Hc];
    int b = blockIdx.x, tid = threadIdx.x;
    for (int k = tid; k < Hc; k += 256) {
        float hv = hn[(size_t)b * Hc + k];
        hs[k] = hv;
        g_h[(size_t)b * Hc + k] = hv;
        g_c[(size_t)b * Hc + k] = cn[(size_t)b * Hc + k];
    }
    __syncthreads();
    if (tid < 128) {
        int o = tid;
        const float4* wr = (const float4*)(Wout + (size_t)o * Hc);
        const float4* hv = (const float4*)hs;
        float s = 0.f;
        for (int k = 0; k < 256; k++) {
            float4 a = hv[k], w = wr[k];
            s += a.x * w.x + a.y * w.y + a.z * w.z + a.w * w.w;
        }
        g_delta[b * Oc + o] = outt[b * Oc + o] - bout[o] - s;
    }
}

// ---------------- persistent kernel: all 1025 phases, grid-synced ----------------
// blocks 0..127 : gates GEMM + LSTM cell for step t       (active for t < Tc)
// blocks 128..131: y_{t-1} = (h_{t-1}@W_out.T + b_out)*m  (active for t > 0)
__global__ void __launch_bounds__(256, 1) persist_kernel(
    const float* __restrict__ x, const int* __restrict__ sl,
    const float* __restrict__ Wout, const float* __restrict__ bout,
    float* __restrict__ out)
{
    __shared__ __align__(128) float as_[2][4096];   // A chunk: 128 rows x 32 k (swizzled pairs)
    __shared__ __align__(128) float ws_[2][1024];   // W chunk: 32 rows x 32 k
    __shared__ float bias_s[32];
    __shared__ int sls[Bc];

    int cb = blockIdx.x, tid = threadIdx.x;
    bool isY = (cb >= 128);

    if (tid < 128) sls[tid] = sl[tid];

    // hoisted per-CTA setup
    const float* wsrc; size_t wstride; int o0 = 0;
    if (!isY) {
        wsrc = g_W + (size_t)cb * 32 * KW; wstride = KW;
        if (tid < 32) bias_s[tid] = g_bp[cb * 32 + tid];
    } else {
        o0 = (cb - 128) * 32;
        wsrc = Wout + (size_t)o0 * Hc; wstride = Hc;
        if (tid < 32) bias_s[tid] = bout[o0 + tid];
    }

    int wr = tid >> 3, wc4 = tid & 7;

    // thread microtile: 4b x 4r
    int w = tid >> 5, l = tid & 31;
    int b0 = ((w << 2) + (l >> 3)) << 2;
    int r0t = (l & 7) << 2;
    int aoff[4], az[4], woff[4], wz[4];
#pragma unroll
    for (int i = 0; i < 4; i++) {
        aoff[i] = (b0 + i) * 32;  az[i] = ((b0 + i) >> 1) & 15;
        woff[i] = (r0t + i) * 32; wz[i] = ((r0t + i) >> 1) & 15;
    }
    __syncthreads();

#pragma unroll 1
    for (int t = 0; t <= Tc; t++) {
        bool active = isY ? (t > 0) : (t < Tc);
        if (active) {
            int par = t & 1;
            const float* hprev = g_h + (size_t)par * (Bc * Hc);
            int NC = isY ? 32 : (t == 0 ? 40 : 36);

            float4 aR[4]; float4 wR;
            auto load_chunk = [&](int kc) {
#pragma unroll
                for (int u = 0; u < 4; u++) {
                    int idx = (u << 8) + tid;
                    int b = idx >> 3, c4 = idx & 7;
                    int k = (kc << 5) + (c4 << 2);
                    const float* src;
                    if (isY || kc < 32)      src = hprev + (size_t)b * Hc + k;
                    else if (kc < 36)        src = x + ((size_t)b * Tc + t) * Ic + (k - 1024);
                    else                     src = g_delta + (size_t)b * Oc + (k - 1152);
                    float4 v = *(const float4*)src;
                    if (!isY && kc >= 32 && kc < 36 && t >= sls[b]) v = make_float4(0.f, 0.f, 0.f, 0.f);
                    aR[u] = v;
                }
                wR = *(const float4*)(wsrc + (size_t)wr * wstride + (kc << 5) + (wc4 << 2));
            };
            auto store_chunk = [&](int s) {
#pragma unroll
                for (int u = 0; u < 4; u++) {
                    int idx = (u << 8) + tid;
                    sts_swz(as_[s], idx >> 3, idx & 7, aR[u]);
                }
                sts_swz(ws_[s], wr, wc4, wR);
            };

            ull acc[16];
#pragma unroll
            for (int i = 0; i < 16; i++) acc[i] = 0ull;

            load_chunk(0);
            for (int kc = 0; kc < NC; kc++) {
                int s = kc & 1;
                store_chunk(s);
                if (kc + 1 < NC) load_chunk(kc + 1);
                __syncthreads();
                const float* A = as_[s];
                const float* W = ws_[s];
#pragma unroll
                for (int kp = 0; kp < 16; kp++) {
                    ull a2[4], w2[4];
#pragma unroll
                    for (int i = 0; i < 4; i++)
                        a2[i] = *(const ull*)(A + aoff[i] + ((kp ^ az[i]) << 1));
#pragma unroll
                    for (int i = 0; i < 4; i++)
                        w2[i] = *(const ull*)(W + woff[i] + ((kp ^ wz[i]) << 1));
#pragma unroll
                    for (int bi = 0; bi < 4; bi++)
#pragma unroll
                        for (int ri = 0; ri < 4; ri++)
                            ffma2(acc[bi * 4 + ri], a2[bi], w2[ri]);
                }
                __syncthreads();
            }

            if (isY) {
#pragma unroll
                for (int bi = 0; bi < 4; bi++)
#pragma unroll
                    for (int ri = 0; ri < 4; ri++) {
                        float2 p = asf2(acc[bi * 4 + ri]);
                        float val = p.x + p.y + bias_s[r0t + ri];
                        int b = b0 + bi, o = o0 + r0t + ri;
                        float m = ((t - 1) < sls[b]) ? 1.0f : 0.0f;
                        out[((size_t)b * Tc + (t - 1)) * Oc + o] = val * m;
                    }
            } else {
                // gate epilogue: stage gates [b][r] in dead GEMM smem, then cell update
                float* gsh = &as_[0][0];   // [128][33]
#pragma unroll
                for (int bi = 0; bi < 4; bi++)
#pragma unroll
                    for (int ri = 0; ri < 4; ri++) {
                        float2 p = asf2(acc[bi * 4 + ri]);
                        gsh[(b0 + bi) * 33 + r0t + ri] = p.x + p.y + bias_s[r0t + ri];
                    }
                __syncthreads();

                int nxt = par ^ 1;
                float* hdst = g_h + (size_t)nxt * (Bc * Hc);
#pragma unroll
                for (int u = 0; u < 4; u++) {
                    int flat = (tid << 2) + u;        // 1024 (b, jj) pairs
                    int b = flat >> 3, jj = flat & 7;
                    float ig = sigm(gsh[b * 33 + jj]);
                    float fg = sigm(gsh[b * 33 + 8 + jj]);
                    float gg = tanhf(gsh[b * 33 + 16 + jj]);
                    float og = sigm(gsh[b * 33 + 24 + jj]);
                    int j = (cb << 3) + jj;
                    size_t idx = (size_t)b * Hc + j;
                    float c = fg * g_c[idx] + ig * gg;
                    g_c[idx] = c;
                    hdst[idx] = og * tanhf(c);
                }
            }
        }
        grid_sync();
    }
}

// ---------------- launch: 3 graph nodes total ----------------
extern "C" void kernel_launch(void* const* d_in, const int* in_sizes, int n_in,
                              void* d_out, int out_size) {
    const float* x    = (const float*)d_in[0];
    const int*   sl   = (const int*)  d_in[1];
    const float* hn   = (const float*)d_in[2];
    const float* cn   = (const float*)d_in[3];
    const float* outt = (const float*)d_in[4];
    const float* Wih  = (const float*)d_in[5];
    const float* Whh  = (const float*)d_in[6];
    const float* bih  = (const float*)d_in[7];
    const float* bhh  = (const float*)d_in[8];
    const float* Wout = (const float*)d_in[9];
    const float* bout = (const float*)d_in[10];
    float* out = (float*)d_out;

    pack_weights<<<128, 256>>>(Wih, Whh, bih, bhh, Wout, bout);
    delta_init<<<128, 256>>>(hn, cn, outt, Wout, bout);
    persist_kernel<<<NBLK, 256>>>(x, sl, Wout, bout, out);
}